// round 7
// baseline (speedup 1.0000x reference)
#include <cuda_runtime.h>

// Shapes fixed by setup_inputs: n=16384, C=32, G=128, N=200000
#define Gdim 128
#define Cdim 32
#define NTHREADS 128
#define NWARPS 4
#define NPW 8              // neighbors per warp
#define INV_SIGMA 10.0f

// 1 if k indices are int64, 0 if int32. Set deterministically each launch.
__device__ int g_k64;

__global__ void detect_k_dtype(const unsigned int* __restrict__ kw) {
    // If k is int64 (LE, values < 200000), every odd 32-bit word is zero.
    const int lane = threadIdx.x & 31;
    const unsigned int w = kw[lane * 2 + 1];
    const unsigned int nz = __ballot_sync(0xffffffffu, w != 0u);
    if (lane == 0) g_k64 = (nz == 0u) ? 1 : 0;
}

// Butterfly reduce-scatter of 8 per-lane values over 32 lanes: 9 shuffles.
// On return every lane's vals[0] holds the warp total of value index
//   j = ((lane>>4)&1)<<2 | ((lane>>3)&1)<<1 | ((lane>>2)&1).
__device__ __forceinline__ float butterfly8(float* vals, int lane) {
    if (lane & 16) {
        #pragma unroll
        for (int i = 0; i < 4; ++i) { float t = vals[i]; vals[i] = vals[i + 4]; vals[i + 4] = t; }
    }
    #pragma unroll
    for (int i = 0; i < 4; ++i) vals[i] += __shfl_xor_sync(0xffffffffu, vals[i + 4], 16);
    if (lane & 8) {
        #pragma unroll
        for (int i = 0; i < 2; ++i) { float t = vals[i]; vals[i] = vals[i + 2]; vals[i + 2] = t; }
    }
    #pragma unroll
    for (int i = 0; i < 2; ++i) vals[i] += __shfl_xor_sync(0xffffffffu, vals[i + 2], 8);
    if (lane & 4) { float t = vals[0]; vals[0] = vals[1]; vals[1] = t; }
    vals[0] += __shfl_xor_sync(0xffffffffu, vals[1], 4);
    vals[0] += __shfl_xor_sync(0xffffffffu, vals[0], 2);
    vals[0] += __shfl_xor_sync(0xffffffffu, vals[0], 1);
    return vals[0];
}

__global__ __launch_bounds__(NTHREADS, 9)
void nc_kernel(const float* __restrict__ x,
               const float* __restrict__ v,
               const void*  __restrict__ kidx,
               const float* __restrict__ X,
               float* __restrict__ out)
{
    __shared__ float s_part[NWARPS][Gdim];   // 2 KB cross-warp partials
    __shared__ float s_num[Cdim];
    __shared__ float s_d2[Cdim];
    __shared__ float s_rvn;                  // 1/||v||, computed by warp 0

    const int row  = blockIdx.x;
    const int tid  = threadIdx.x;
    const int wid  = tid >> 5;
    const int lane = tid & 31;
    const int k64  = g_k64;

    // Every warp loads x,v rows directly (L1 broadcast hits after 1st warp).
    const float4 xv = reinterpret_cast<const float4*>(x + (size_t)row * Gdim)[lane];
    const float4 vv = reinterpret_cast<const float4*>(v + (size_t)row * Gdim)[lane];

    // 1/||v|| in warp 0 only; published via smem through the barrier below.
    if (wid == 0) {
        float ss = vv.x * vv.x + vv.y * vv.y + vv.z * vv.z + vv.w * vv.w;
        #pragma unroll
        for (int o = 16; o; o >>= 1)
            ss += __shfl_xor_sync(0xffffffffu, ss, o);
        if (lane == 0) s_rvn = rsqrtf(ss);
    }

    // Byte offsets of this warp's 8 neighbor rows (u32: 200000*512 < 2^31).
    unsigned int off[NPW];
    if (k64) {
        const longlong2* kp = reinterpret_cast<const longlong2*>(
            reinterpret_cast<const long long*>(kidx) + (size_t)row * Cdim + wid * NPW);
        #pragma unroll
        for (int j = 0; j < 4; ++j) {
            const longlong2 p = kp[j];
            off[2 * j]     = (unsigned int)p.x << 9;
            off[2 * j + 1] = (unsigned int)p.y << 9;
        }
    } else {
        const int4* kp = reinterpret_cast<const int4*>(
            reinterpret_cast<const int*>(kidx) + (size_t)row * Cdim + wid * NPW);
        const int4 a = kp[0], b = kp[1];
        off[0] = (unsigned int)a.x << 9; off[1] = (unsigned int)a.y << 9;
        off[2] = (unsigned int)a.z << 9; off[3] = (unsigned int)a.w << 9;
        off[4] = (unsigned int)b.x << 9; off[5] = (unsigned int)b.y << 9;
        off[6] = (unsigned int)b.z << 9; off[7] = (unsigned int)b.w << 9;
    }

    // Issue all 8 gather row loads (MLP=8), deltas in scalar registers.
    const char* Xb = reinterpret_cast<const char*>(X);
    float4 dl[NPW];
    {
        float4 Xl[NPW];
        #pragma unroll
        for (int j = 0; j < NPW; ++j)
            Xl[j] = *reinterpret_cast<const float4*>(Xb + off[j] + (lane << 4));
        #pragma unroll
        for (int j = 0; j < NPW; ++j) {
            dl[j].x = Xl[j].x - xv.x; dl[j].y = Xl[j].y - xv.y;
            dl[j].z = Xl[j].z - xv.z; dl[j].w = Xl[j].w - xv.w;
        }
    }

    // Pass 1: num_j = dot(v, delta_j), butterfly, publish.
    {
        float nums[NPW];
        #pragma unroll
        for (int j = 0; j < NPW; ++j)
            nums[j] = fmaf(dl[j].x, vv.x, fmaf(dl[j].y, vv.y, fmaf(dl[j].z, vv.z, dl[j].w * vv.w)));
        const float r = butterfly8(nums, lane);
        if ((lane & 3) == 0) {
            const int j = (((lane >> 4) & 1) << 2) | (((lane >> 3) & 1) << 1) | ((lane >> 2) & 1);
            s_num[wid * NPW + j] = r;
        }
    }
    // Pass 2: d2_j = ||delta_j||^2, butterfly, publish.
    {
        float d2s[NPW];
        #pragma unroll
        for (int j = 0; j < NPW; ++j)
            d2s[j] = fmaf(dl[j].x, dl[j].x, fmaf(dl[j].y, dl[j].y, fmaf(dl[j].z, dl[j].z, dl[j].w * dl[j].w)));
        const float r = butterfly8(d2s, lane);
        if ((lane & 3) == 0) {
            const int j = (((lane >> 4) & 1) << 2) | (((lane >> 3) & 1) << 1) | ((lane >> 2) & 1);
            s_d2[wid * NPW + j] = r;
        }
    }
    __syncthreads();

    // Weights, redundantly per warp (lane l = neighbor l), fast math:
    //   cs = num * rsqrt(d2) * (1/||v||); Tv = __expf(10*cs)-1;
    //   w  = (Tv - mean(Tv_norm-pre)) scaled by 1/sum|Tv|.
    float wl;
    {
        const float rvn = s_rvn;
        const float d2 = fmaxf(s_d2[lane], 1e-24f);
        const float cs = s_num[lane] * rsqrtf(d2) * rvn;
        const float tv = __expf(cs * INV_SIGMA) - 1.0f;
        // reduce-scatter of (sum|tv|, sum tv): 6 shuffles + 1 exchange.
        const float sa = fabsf(tv);
        float keep = (lane & 16) ? tv : sa;
        float send = (lane & 16) ? sa : tv;
        keep += __shfl_xor_sync(0xffffffffu, send, 16);
        keep += __shfl_xor_sync(0xffffffffu, keep, 8);
        keep += __shfl_xor_sync(0xffffffffu, keep, 4);
        keep += __shfl_xor_sync(0xffffffffu, keep, 2);
        keep += __shfl_xor_sync(0xffffffffu, keep, 1);
        const float other = __shfl_xor_sync(0xffffffffu, keep, 16);
        const float sa_t = (lane & 16) ? other : keep;
        const float st_t = (lane & 16) ? keep  : other;
        wl = (tv - st_t * (1.0f / (float)Cdim)) * __fdividef(1.0f, sa_t);
    }

    // Warp partial: sum_j w_j * delta_j  (scalar FMA, regs -> smem)
    {
        float4 acc = make_float4(0.f, 0.f, 0.f, 0.f);
        #pragma unroll
        for (int j = 0; j < NPW; ++j) {
            const float wj = __shfl_sync(0xffffffffu, wl, wid * NPW + j);
            acc.x = fmaf(wj, dl[j].x, acc.x);
            acc.y = fmaf(wj, dl[j].y, acc.y);
            acc.z = fmaf(wj, dl[j].z, acc.z);
            acc.w = fmaf(wj, dl[j].w, acc.w);
        }
        reinterpret_cast<float4*>(s_part[wid])[lane] = acc;
    }
    __syncthreads();

    // Reduce 4 warp partials (128 threads, one g each), coalesced store.
    {
        float r = (s_part[0][tid] + s_part[1][tid]) + (s_part[2][tid] + s_part[3][tid]);
        out[(size_t)row * Gdim + tid] = r;
    }
}

extern "C" void kernel_launch(void* const* d_in, const int* in_sizes, int n_in,
                              void* d_out, int out_size) {
    const float* x = (const float*)d_in[0];
    const float* v = (const float*)d_in[1];
    const void*  k = d_in[2];
    const float* X = (const float*)d_in[3];
    float* out = (float*)d_out;

    const int n = in_sizes[0] / Gdim;   // 16384

    detect_k_dtype<<<1, 32>>>((const unsigned int*)k);
    nc_kernel<<<n, NTHREADS>>>(x, v, k, X, out);
}